// round 13
// baseline (speedup 1.0000x reference)
#include <cuda_runtime.h>
#include <cuda_fp16.h>
#include <cstdint>
#include <math.h>

#define B_SZ     16384
#define T_SZ     10
#define H_SZ     256
#define G_SZ     1024
#define N_LABELS 500
#define ROWS     (B_SZ * T_SZ)     // 163840
#define XPAD     64
#define XGSTRIDE 10240             // T_SZ * G_SZ

typedef unsigned long long u64;
typedef unsigned int u32;
typedef __half fp16;

// ---------------- device scratch (no allocations allowed) --------------------
__device__ fp16  g_x   [(size_t)ROWS * XPAD];      // gathered input [b*T+t][64]
__device__ fp16  g_xg  [(size_t)ROWS * G_SZ];      // gate preacts (fp16, permuted, bias folded)
__device__ fp16  g_h1  [(size_t)ROWS * H_SZ];      // layer0 h, [t][b][256] (doubles as L0 state)
__device__ fp16  g_h2a [(size_t)B_SZ * H_SZ];      // layer1 h ping-pong
__device__ fp16  g_h2b [(size_t)B_SZ * H_SZ];
__device__ float g_c0  [(size_t)B_SZ * H_SZ];
__device__ float g_c1  [(size_t)B_SZ * H_SZ];
__device__ float g_bias0[G_SZ];
__device__ float g_bias1[G_SZ];
// weight tile images (fp16, pre-swizzled): [tile*nkc+kc][256 rows][64 cols]
__device__ fp16 g_wih0[4 * 1 * 16384];
__device__ fp16 g_whh0[4 * 4 * 16384];
__device__ fp16 g_wih1[4 * 4 * 16384];
__device__ fp16 g_whh1[4 * 4 * 16384];
__device__ fp16 g_wout[2 * 4 * 16384];

// ---------------- PTX helpers ------------------------------------------------
__device__ __forceinline__ u32 smem_u32(const void* p) {
    u32 a; asm("{ .reg .u64 t; cvta.to.shared.u64 t, %1; cvt.u32.u64 %0, t; }"
               : "=r"(a) : "l"(p));
    return a;
}
__device__ __forceinline__ void cp16(u32 dst, const void* src) {
    asm volatile("cp.async.cg.shared.global [%0], [%1], 16;" :: "r"(dst), "l"(src));
}
__device__ __forceinline__ void cp_commit() { asm volatile("cp.async.commit_group;"); }
template <int N> __device__ __forceinline__ void cp_wait() {
    asm volatile("cp.async.wait_group %0;" :: "n"(N));
}
__device__ __forceinline__ void ldm4(u32& r0, u32& r1, u32& r2, u32& r3, u32 addr) {
    asm volatile("ldmatrix.sync.aligned.m8n8.x4.shared.b16 {%0,%1,%2,%3}, [%4];"
                 : "=r"(r0), "=r"(r1), "=r"(r2), "=r"(r3) : "r"(addr));
}
__device__ __forceinline__ void mma16(float* d, const u32* a, const u32* b) {
    asm volatile("mma.sync.aligned.m16n8k16.row.col.f32.f16.f16.f32 "
                 "{%0,%1,%2,%3}, {%4,%5,%6,%7}, {%8,%9}, {%0,%1,%2,%3};"
                 : "+f"(d[0]), "+f"(d[1]), "+f"(d[2]), "+f"(d[3])
                 : "r"(a[0]), "r"(a[1]), "r"(a[2]), "r"(a[3]), "r"(b[0]), "r"(b[1]));
}
// HW tanh (sm_75+): 1 MUFU op, rel err ~2^-11 (same order as fp16 rounding already in chain)
__device__ __forceinline__ float tanh_ap(float x) {
    float y; asm("tanh.approx.f32 %0, %1;" : "=f"(y) : "f"(x)); return y;
}
__device__ __forceinline__ float sig_ap(float x) {
    return fmaf(tanh_ap(0.5f * x), 0.5f, 0.5f);
}

// ---------------- prep + gather merged (ONE launch) ---------------------------
__device__ __forceinline__ void fill_img(fp16* img, long l, int nkc,
                                         const float* W, int Kw, int Nrows, int perm) {
    int c = (int)(l & 63);
    int r = (int)((l >> 6) & 255);
    long tc = l >> 14;
    int kc = (int)(tc % nkc), nt = (int)(tc / nkc);
    int p = nt * 256 + r;
    int n = perm ? ((p & 3) * 256 + (p >> 2)) : p;
    int k = kc * 64 + c;
    float v = (n < Nrows && k < Kw) ? W[(size_t)n * Kw + k] : 0.f;
    size_t pos = ((size_t)tc * 256 + r) * 64 + (size_t)((((c >> 3) ^ (r & 7)) << 3) | (c & 7));
    img[pos] = __float2half(v);
}

#define SEG0 65536L                  // wih0
#define SEG1 (SEG0 + 262144L)        // whh0
#define SEG2 (SEG1 + 262144L)        // wih1
#define SEG3 (SEG2 + 262144L)        // whh1
#define SEG4 (SEG3 + 131072L)        // wout
#define SEG5 (SEG4 + 1024L)          // biases
#define TOTAL_PG (SEG5 + (long)ROWS * XPAD)

__global__ void prep_gather(const float* __restrict__ Wih0, const float* __restrict__ Whh0,
                            const float* __restrict__ Wih1, const float* __restrict__ Whh1,
                            const float* __restrict__ Wout,
                            const float* __restrict__ bih0, const float* __restrict__ bhh0,
                            const float* __restrict__ bih1, const float* __restrict__ bhh1,
                            const int* __restrict__ car, const int* __restrict__ reg,
                            const int* __restrict__ poi, const int* __restrict__ week,
                            const int* __restrict__ timei,
                            const float* __restrict__ ce, const float* __restrict__ re,
                            const float* __restrict__ pe, const float* __restrict__ we,
                            const float* __restrict__ te) {
    long id = (long)blockIdx.x * blockDim.x + threadIdx.x;
    if (id < SEG0)      fill_img(g_wih0, id,        1, Wih0, 39,  1024, 1);
    else if (id < SEG1) fill_img(g_whh0, id - SEG0, 4, Whh0, 256, 1024, 1);
    else if (id < SEG2) fill_img(g_wih1, id - SEG1, 4, Wih1, 256, 1024, 1);
    else if (id < SEG3) fill_img(g_whh1, id - SEG2, 4, Whh1, 256, 1024, 1);
    else if (id < SEG4) fill_img(g_wout, id - SEG3, 4, Wout, 256, 500,  0);
    else if (id < SEG5) {
        int p = (int)(id - SEG4);
        int j = p >> 2, g = p & 3, n = g * 256 + j;
        g_bias0[p] = bih0[n] + bhh0[n];
        g_bias1[p] = bih1[n] + bhh1[n];
    } else if (id < TOTAL_PG) {
        long i = id - SEG5;
        long r = i / XPAD; int j = (int)(i % XPAD);
        float v = 0.f;
        if      (j < 16) v = ce[(size_t)car  [r] * 16 + j];
        else if (j < 24) v = re[(size_t)reg  [r] * 8  + (j - 16)];
        else if (j < 28) v = pe[(size_t)poi  [r] * 4  + (j - 24)];
        else if (j < 31) v = we[(size_t)week [r] * 3  + (j - 28)];
        else if (j < 39) v = te[(size_t)timei[r] * 8  + (j - 31)];
        g_x[i] = __float2half(v);
    }
}

// ---------------- GEMM config ------------------------------------------------
#define STG_BYTES 32768
#define SM_BYTES  (2 * STG_BYTES)             // 65536 (projections/head)
#define XG_BYTES  32768
#define SMR_BYTES (2 * STG_BYTES + XG_BYTES)  // 98304 (rec kernel)

#define ACC_DECL                                                                       \
    float acc[4][4][4];                                                                \
    _Pragma("unroll") for (int a_ = 0; a_ < 4; a_++)                                   \
    _Pragma("unroll") for (int b_ = 0; b_ < 4; b_++)                                   \
    _Pragma("unroll") for (int e_ = 0; e_ < 4; e_++) acc[a_][b_][e_] = 0.f;

#define GEMM_COMPUTE_CHUNK(aBase, bBase)                                               \
    _Pragma("unroll")                                                                  \
    for (int k16 = 0; k16 < 4; ++k16) {                                                \
        const int kb8 = k16 * 2 + lk;                                                  \
        u32 bh[4][2];                                                                  \
        _Pragma("unroll")                                                              \
        for (int blk = 0; blk < 2; ++blk) {                                            \
            int row = n_w + blk * 16 + lrow;                                           \
            u32 ad = (bBase) + ((row * 64 + ((kb8 ^ (row & 7)) << 3)) << 1);           \
            u32 r0_, r1_, r2_, r3_;                                                    \
            ldm4(r0_, r1_, r2_, r3_, ad);                                              \
            bh[blk * 2][0] = r0_; bh[blk * 2][1] = r2_;                                \
            bh[blk * 2 + 1][0] = r1_; bh[blk * 2 + 1][1] = r3_;                        \
        }                                                                              \
        _Pragma("unroll")                                                              \
        for (int mt = 0; mt < 4; ++mt) {                                               \
            int row = m_w + mt * 16 + lrow;                                            \
            u32 ad = (aBase) + ((row * 64 + ((kb8 ^ (row & 7)) << 3)) << 1);           \
            u32 af[4];                                                                 \
            ldm4(af[0], af[1], af[2], af[3], ad);                                      \
            _Pragma("unroll")                                                          \
            for (int nt = 0; nt < 4; ++nt) mma16(acc[mt][nt], af, bh[nt]);             \
        }                                                                              \
    }

// ---------------- recurrent GEMM + fused LSTM cell -----------------------------
// gates = h_prev @ W^T + xg_t (addend prefetched to SMEM during mainloop).
__global__ void __launch_bounds__(256, 2)
gemm_rec(const fp16* __restrict__ A, fp16* __restrict__ hout,
         const fp16* __restrict__ W,
         const fp16* __restrict__ xgs, int rowStride,   // xgs = xg slice for step t
         float* __restrict__ c)
{
    extern __shared__ __align__(1024) char sm[];
    const u32 sb = smem_u32(sm);
    const u32 XB = sb + 2 * STG_BYTES;
    char* smx = sm + 2 * STG_BYTES;
    const int tid = threadIdx.x, wid = tid >> 5, lid = tid & 31;
    const int m0 = blockIdx.y * 128;
    const int n0 = blockIdx.x * 128;
    const int tile = n0 >> 8, rowbase = n0 & 255;
    const int m_w = (wid >> 2) * 64, n_w = (wid & 2 ? 64 : 0) + (wid & 1) * 32;
    const int au = tid & 7, ar = tid >> 3;
    const int lrow = lid & 15, lk = lid >> 4;
    const int odd = lid & 1;

    ACC_DECL

    // xg tile prefetch: 128 rows x 128 cols fp16 = 32KB, coalesced 16B chunks.
    {
        int rowL = tid >> 4;
        int coloff = (tid & 15) * 8;
#pragma unroll
        for (int i = 0; i < 8; i++) {
            int row = rowL + i * 16;
            cp16(XB + (u32)((row * 128 + coloff) * 2),
                 xgs + (size_t)(m0 + row) * rowStride + n0 + coloff);
        }
    }

    auto load0 = [&](int stg, int kc) {
        u32 base = sb + stg * STG_BYTES;
#pragma unroll
        for (int i = 0; i < 4; i++) {
            int r = ar + i * 32;
            u32 d = base + ((r * 64 + ((au ^ (r & 7)) << 3)) << 1);
            cp16(d, A + (size_t)(m0 + r) * H_SZ + kc * 64 + au * 8);
        }
        const size_t ib = (size_t)(tile * 4 + kc) * 16384 + (size_t)rowbase * 64;
#pragma unroll
        for (int i = 0; i < 4; i++) {
            int j = tid + i * 256;
            cp16(base + 16384 + j * 16, W + ib + (size_t)j * 8);
        }
        cp_commit();
    };
    load0(0, 0);
#pragma unroll 1
    for (int kc = 0; kc < 4; ++kc) {
        if (kc + 1 < 4) { load0((kc + 1) & 1, kc + 1); cp_wait<1>(); }
        else            { cp_wait<0>(); }
        __syncthreads();
        const u32 aBase = sb + (kc & 1) * STG_BYTES;
        const u32 bBase = aBase + 16384;
        GEMM_COMPUTE_CHUNK(aBase, bBase)
        __syncthreads();
    }

    // fused LSTM cell epilogue (xg from SMEM; HW tanh.approx gate math)
#pragma unroll
    for (int mt = 0; mt < 4; ++mt) {
        int r0 = m0 + m_w + mt * 16 + (lid >> 2);
#pragma unroll
        for (int nt = 0; nt < 4; ++nt) {
            float* a4 = acc[mt][nt];
            int p = n0 + n_w + nt * 8 + (lid & 3) * 2;
            int j = p >> 2;
            float s0 = odd ? a4[0] : a4[2];
            float s1 = odd ? a4[1] : a4[3];
            float r0v = __shfl_xor_sync(0xFFFFFFFFu, s0, 1);
            float r1v = __shfl_xor_sync(0xFFFFFFFFu, s1, 1);
            float gi, gf, gg, go;
            int row;
            if (odd) { gi = r0v;  gf = r1v;  gg = a4[2]; go = a4[3]; row = r0 + 8; }
            else     { gi = a4[0]; gf = a4[1]; gg = r0v; go = r1v;  row = r0; }
            int rowL = row - m0;
            int coloff = (p - n0) & ~3;
            const fp16* xs = (const fp16*)(smx + (rowL * 128 + coloff) * 2);
            float2 f01 = __half22float2(*(const __half2*)(xs));
            float2 f23 = __half22float2(*(const __half2*)(xs + 2));
            gi = sig_ap(gi + f01.x);
            gf = sig_ap(gf + f01.y);
            gg = tanh_ap(gg + f23.x);
            go = sig_ap(go + f23.y);
            size_t ci = (size_t)row * H_SZ + j;
            float cn = gf * c[ci] + gi * gg;
            float hn = go * tanh_ap(cn);
            c[ci] = cn;
            hout[ci] = __float2half(hn);
        }
    }
}

// ---------------- generic GEMM (projections fp16-out, head fp32-out) -----------
template <typename OutT>
__global__ void __launch_bounds__(256)
gemm_mma(const fp16* __restrict__ A, int lda,
         const fp16* __restrict__ W, int nkc,
         const float* __restrict__ bias,
         OutT* __restrict__ C, int ldc, int Nvalid)
{
    extern __shared__ __align__(1024) char sm[];
    const u32 sb = smem_u32(sm);
    const int tid = threadIdx.x, wid = tid >> 5, lid = tid & 31;
    const int m0 = blockIdx.y * 128;
    const int n0 = blockIdx.x * 128;
    const int tile = n0 >> 8, rowbase = n0 & 255;
    const int m_w = (wid >> 2) * 64, n_w = (wid & 2 ? 64 : 0) + (wid & 1) * 32;
    const int au = tid & 7, ar = tid >> 3;
    const int lrow = lid & 15, lk = lid >> 4;

    ACC_DECL

    auto load_stage = [&](int s, int kc) {
        u32 base = sb + s * STG_BYTES;
#pragma unroll
        for (int i = 0; i < 4; i++) {
            int r = ar + i * 32;
            u32 d = base + ((r * 64 + ((au ^ (r & 7)) << 3)) << 1);
            cp16(d, A + (size_t)(m0 + r) * lda + (size_t)kc * 64 + au * 8);
        }
        const size_t ib = (size_t)(tile * nkc + kc) * 16384 + (size_t)rowbase * 64;
#pragma unroll
        for (int i = 0; i < 4; i++) {
            int j = tid + i * 256;
            cp16(base + 16384 + j * 16, W + ib + (size_t)j * 8);
        }
        cp_commit();
    };
    load_stage(0, 0);
    for (int kc = 0; kc < nkc; ++kc) {
        if (kc + 1 < nkc) { load_stage((kc + 1) & 1, kc + 1); cp_wait<1>(); }
        else              { cp_wait<0>(); }
        __syncthreads();
        const u32 aBase = sb + (kc & 1) * STG_BYTES;
        const u32 bBase = aBase + 16384;
        GEMM_COMPUTE_CHUNK(aBase, bBase)
        __syncthreads();
    }

#pragma unroll
    for (int mt = 0; mt < 4; ++mt) {
        int r0 = m0 + m_w + mt * 16 + (lid >> 2);
#pragma unroll
        for (int nt = 0; nt < 4; ++nt) {
            int cN = n0 + n_w + nt * 8 + (lid & 3) * 2;
            if (cN < Nvalid) {
                float bx = bias[cN], by = bias[cN + 1];
                float a0 = acc[mt][nt][0] + bx, a1 = acc[mt][nt][1] + by;
                float a2 = acc[mt][nt][2] + bx, a3 = acc[mt][nt][3] + by;
                if constexpr (sizeof(OutT) == 2) {
                    *(__half2*)((fp16*)C + (size_t)r0 * ldc + cN) = __floats2half2_rn(a0, a1);
                    *(__half2*)((fp16*)C + (size_t)(r0 + 8) * ldc + cN) = __floats2half2_rn(a2, a3);
                } else {
                    *(float2*)((float*)C + (size_t)r0 * ldc + cN) = make_float2(a0, a1);
                    *(float2*)((float*)C + (size_t)(r0 + 8) * ldc + cN) = make_float2(a2, a3);
                }
            }
        }
    }
}

// ---------------- t=0 cell (gates = xg_0, c = 0) -------------------------------
__global__ void cell_t0(const fp16* __restrict__ xg, int rowStride,
                        float* __restrict__ c, fp16* __restrict__ hout) {
    int idx = blockIdx.x * blockDim.x + threadIdx.x;
    if (idx >= B_SZ * H_SZ) return;
    int b = idx >> 8, j = idx & 255;
    const fp16* xrow = xg + (size_t)b * rowStride + 4 * j;
    float2 f01 = __half22float2(*(const __half2*)(xrow));
    float2 f23 = __half22float2(*(const __half2*)(xrow + 2));
    float gi = sig_ap(f01.x);
    float gf = sig_ap(f01.y);   // unused product with c=0 but keep for symmetry
    float gg = tanh_ap(f23.x);
    float go = sig_ap(f23.y);
    (void)gf;
    float cn = gi * gg;
    float hn = go * tanh_ap(cn);
    c[idx] = cn;
    hout[idx] = __float2half(hn);
}

// ---------------- launch ------------------------------------------------------
extern "C" void kernel_launch(void* const* d_in, const int* in_sizes, int n_in,
                              void* d_out, int out_size)
{
    const int*   car    = (const int*)  d_in[0];
    const int*   reg    = (const int*)  d_in[1];
    const int*   poi    = (const int*)  d_in[2];
    const int*   week   = (const int*)  d_in[3];
    const int*   timei  = (const int*)  d_in[4];
    const float* car_e  = (const float*)d_in[5];
    const float* reg_e  = (const float*)d_in[6];
    const float* poi_e  = (const float*)d_in[7];
    const float* week_e = (const float*)d_in[8];
    const float* time_e = (const float*)d_in[9];
    const float* Wih0   = (const float*)d_in[10];
    const float* Whh0   = (const float*)d_in[11];
    const float* bih0   = (const float*)d_in[12];
    const float* bhh0   = (const float*)d_in[13];
    const float* Wih1   = (const float*)d_in[14];
    const float* Whh1   = (const float*)d_in[15];
    const float* bih1   = (const float*)d_in[16];
    const float* bhh1   = (const float*)d_in[17];
    const float* Wout   = (const float*)d_in[18];
    const float* bout   = (const float*)d_in[19];
    float* out = (float*)d_out;

    fp16 *x, *xg, *h1, *h2a, *h2b, *wih0, *whh0, *wih1, *whh1, *wout;
    float *c0, *c1, *bias0, *bias1;
    cudaGetSymbolAddress((void**)&x,     g_x);
    cudaGetSymbolAddress((void**)&xg,    g_xg);
    cudaGetSymbolAddress((void**)&h1,    g_h1);
    cudaGetSymbolAddress((void**)&h2a,   g_h2a);
    cudaGetSymbolAddress((void**)&h2b,   g_h2b);
    cudaGetSymbolAddress((void**)&c0,    g_c0);
    cudaGetSymbolAddress((void**)&c1,    g_c1);
    cudaGetSymbolAddress((void**)&bias0, g_bias0);
    cudaGetSymbolAddress((void**)&bias1, g_bias1);
    cudaGetSymbolAddress((void**)&wih0,  g_wih0);
    cudaGetSymbolAddress((void**)&whh0,  g_whh0);
    cudaGetSymbolAddress((void**)&wih1,  g_wih1);
    cudaGetSymbolAddress((void**)&whh1,  g_whh1);
    cudaGetSymbolAddress((void**)&wout,  g_wout);

    cudaFuncSetAttribute(gemm_mma<fp16>,  cudaFuncAttributeMaxDynamicSharedMemorySize, SM_BYTES);
    cudaFuncSetAttribute(gemm_mma<float>, cudaFuncAttributeMaxDynamicSharedMemorySize, SM_BYTES);
    cudaFuncSetAttribute(gemm_rec,        cudaFuncAttributeMaxDynamicSharedMemorySize, SMR_BYTES);

    const dim3 recGrid(8, B_SZ / 128);

    // 1: prep + gather
    prep_gather<<<(int)((TOTAL_PG + 255) / 256), 256>>>(
        Wih0, Whh0, Wih1, Whh1, Wout, bih0, bhh0, bih1, bhh1,
        car, reg, poi, week, timei, car_e, reg_e, poi_e, week_e, time_e);
    // 2: layer0 input projection (fp16 out, bias folded; rows b-major)
    gemm_mma<fp16><<<dim3(8, ROWS / 128), 256, SM_BYTES>>>(
        x, XPAD, wih0, 1, bias0, xg, G_SZ, G_SZ);
    // 3: layer0 t=0 cell -> h1[0]
    cell_t0<<<(B_SZ * H_SZ) / 256, 256>>>(xg, XGSTRIDE, c0, h1);
    // 4..12: layer0 t=1..9 (h state lives directly in h1[t])
    for (int t = 1; t < T_SZ; ++t)
        gemm_rec<<<recGrid, 256, SMR_BYTES>>>(
            h1 + (size_t)(t - 1) * B_SZ * H_SZ, h1 + (size_t)t * B_SZ * H_SZ,
            whh0, xg + (size_t)t * G_SZ, XGSTRIDE, c0);
    // 13: layer1 input projection (h1 rows t-major; xg reused, rows t-major)
    gemm_mma<fp16><<<dim3(8, ROWS / 128), 256, SM_BYTES>>>(
        h1, H_SZ, wih1, 4, bias1, xg, G_SZ, G_SZ);
    // 14: layer1 t=0 cell
    cell_t0<<<(B_SZ * H_SZ) / 256, 256>>>(xg, G_SZ, c1, h2a);
    // 15..23: layer1 t=1..9
    {
        fp16* hb[2] = { h2a, h2b };
        for (int t = 1; t < T_SZ; ++t)
            gemm_rec<<<recGrid, 256, SMR_BYTES>>>(
                hb[(t - 1) & 1], hb[t & 1], whh1,
                xg + (size_t)t * B_SZ * G_SZ, G_SZ, c1);
    }
    // 24: output head (h_last = h2b since t=9 is odd)
    gemm_mma<float><<<dim3(4, B_SZ / 128), 256, SM_BYTES>>>(
        h2b, H_SZ, wout, 4, bout, out, N_LABELS, N_LABELS);
}

// round 14
// speedup vs baseline: 1.3779x; 1.3779x over previous
#include <cuda_runtime.h>
#include <cuda_fp16.h>
#include <cstdint>
#include <math.h>

#define B_SZ     16384
#define T_SZ     10
#define H_SZ     256
#define G_SZ     1024
#define N_LABELS 500
#define ROWS     (B_SZ * T_SZ)     // 163840
#define XPAD     64
#define XGSTRIDE 10240             // T_SZ * G_SZ

typedef unsigned long long u64;
typedef unsigned int u32;
typedef __half fp16;

// ---------------- device scratch (no allocations allowed) --------------------
__device__ fp16  g_x   [(size_t)ROWS * XPAD];      // gathered input [b*T+t][64]
__device__ fp16  g_xg  [(size_t)ROWS * G_SZ];      // gate preacts (fp16, permuted, bias folded)
__device__ fp16  g_h1  [(size_t)ROWS * H_SZ];      // layer0 h, [t][b][256] (doubles as L0 state)
__device__ fp16  g_h2a [(size_t)B_SZ * H_SZ];      // layer1 h ping-pong
__device__ fp16  g_h2b [(size_t)B_SZ * H_SZ];
__device__ float g_c0  [(size_t)B_SZ * H_SZ];
__device__ float g_c1  [(size_t)B_SZ * H_SZ];
__device__ float g_bias0[G_SZ];
__device__ float g_bias1[G_SZ];
// weight tile images (fp16, pre-swizzled): [tile*nkc+kc][256 rows][64 cols]
__device__ fp16 g_wih0[4 * 1 * 16384];
__device__ fp16 g_whh0[4 * 4 * 16384];
__device__ fp16 g_wih1[4 * 4 * 16384];
__device__ fp16 g_whh1[4 * 4 * 16384];
__device__ fp16 g_wout[2 * 4 * 16384];

// ---------------- PTX helpers ------------------------------------------------
__device__ __forceinline__ u32 smem_u32(const void* p) {
    u32 a; asm("{ .reg .u64 t; cvta.to.shared.u64 t, %1; cvt.u32.u64 %0, t; }"
               : "=r"(a) : "l"(p));
    return a;
}
__device__ __forceinline__ void cp16(u32 dst, const void* src) {
    asm volatile("cp.async.cg.shared.global [%0], [%1], 16;" :: "r"(dst), "l"(src));
}
__device__ __forceinline__ void cp_commit() { asm volatile("cp.async.commit_group;"); }
template <int N> __device__ __forceinline__ void cp_wait() {
    asm volatile("cp.async.wait_group %0;" :: "n"(N));
}
__device__ __forceinline__ void ldm4(u32& r0, u32& r1, u32& r2, u32& r3, u32 addr) {
    asm volatile("ldmatrix.sync.aligned.m8n8.x4.shared.b16 {%0,%1,%2,%3}, [%4];"
                 : "=r"(r0), "=r"(r1), "=r"(r2), "=r"(r3) : "r"(addr));
}
__device__ __forceinline__ void mma16(float* d, const u32* a, const u32* b) {
    asm volatile("mma.sync.aligned.m16n8k16.row.col.f32.f16.f16.f32 "
                 "{%0,%1,%2,%3}, {%4,%5,%6,%7}, {%8,%9}, {%0,%1,%2,%3};"
                 : "+f"(d[0]), "+f"(d[1]), "+f"(d[2]), "+f"(d[3])
                 : "r"(a[0]), "r"(a[1]), "r"(a[2]), "r"(a[3]), "r"(b[0]), "r"(b[1]));
}
// Fast gate math via ex2.approx/rcp.approx (the SAME HW paths libm expf already
// used in the proven-fast R12 kernel). tanh.approx.f32 measured pathological on
// this sm_100 part (R13: 3.4x kernel slowdown) — do NOT use it.
__device__ __forceinline__ float sig_fast(float x) {
    return __fdividef(1.f, 1.f + __expf(-x));
}
__device__ __forceinline__ float tanh_fast(float x) {
    return 1.f - __fdividef(2.f, __expf(2.f * x) + 1.f);
}

// ---------------- prep + gather merged (ONE launch) ---------------------------
__device__ __forceinline__ void fill_img(fp16* img, long l, int nkc,
                                         const float* W, int Kw, int Nrows, int perm) {
    int c = (int)(l & 63);
    int r = (int)((l >> 6) & 255);
    long tc = l >> 14;
    int kc = (int)(tc % nkc), nt = (int)(tc / nkc);
    int p = nt * 256 + r;
    int n = perm ? ((p & 3) * 256 + (p >> 2)) : p;
    int k = kc * 64 + c;
    float v = (n < Nrows && k < Kw) ? W[(size_t)n * Kw + k] : 0.f;
    size_t pos = ((size_t)tc * 256 + r) * 64 + (size_t)((((c >> 3) ^ (r & 7)) << 3) | (c & 7));
    img[pos] = __float2half(v);
}

#define SEG0 65536L                  // wih0
#define SEG1 (SEG0 + 262144L)        // whh0
#define SEG2 (SEG1 + 262144L)        // wih1
#define SEG3 (SEG2 + 262144L)        // whh1
#define SEG4 (SEG3 + 131072L)        // wout
#define SEG5 (SEG4 + 1024L)          // biases
#define TOTAL_PG (SEG5 + (long)ROWS * XPAD)

__global__ void prep_gather(const float* __restrict__ Wih0, const float* __restrict__ Whh0,
                            const float* __restrict__ Wih1, const float* __restrict__ Whh1,
                            const float* __restrict__ Wout,
                            const float* __restrict__ bih0, const float* __restrict__ bhh0,
                            const float* __restrict__ bih1, const float* __restrict__ bhh1,
                            const int* __restrict__ car, const int* __restrict__ reg,
                            const int* __restrict__ poi, const int* __restrict__ week,
                            const int* __restrict__ timei,
                            const float* __restrict__ ce, const float* __restrict__ re,
                            const float* __restrict__ pe, const float* __restrict__ we,
                            const float* __restrict__ te) {
    long id = (long)blockIdx.x * blockDim.x + threadIdx.x;
    if (id < SEG0)      fill_img(g_wih0, id,        1, Wih0, 39,  1024, 1);
    else if (id < SEG1) fill_img(g_whh0, id - SEG0, 4, Whh0, 256, 1024, 1);
    else if (id < SEG2) fill_img(g_wih1, id - SEG1, 4, Wih1, 256, 1024, 1);
    else if (id < SEG3) fill_img(g_whh1, id - SEG2, 4, Whh1, 256, 1024, 1);
    else if (id < SEG4) fill_img(g_wout, id - SEG3, 4, Wout, 256, 500,  0);
    else if (id < SEG5) {
        int p = (int)(id - SEG4);
        int j = p >> 2, g = p & 3, n = g * 256 + j;
        g_bias0[p] = bih0[n] + bhh0[n];
        g_bias1[p] = bih1[n] + bhh1[n];
    } else if (id < TOTAL_PG) {
        long i = id - SEG5;
        long r = i / XPAD; int j = (int)(i % XPAD);
        float v = 0.f;
        if      (j < 16) v = ce[(size_t)car  [r] * 16 + j];
        else if (j < 24) v = re[(size_t)reg  [r] * 8  + (j - 16)];
        else if (j < 28) v = pe[(size_t)poi  [r] * 4  + (j - 24)];
        else if (j < 31) v = we[(size_t)week [r] * 3  + (j - 28)];
        else if (j < 39) v = te[(size_t)timei[r] * 8  + (j - 31)];
        g_x[i] = __float2half(v);
    }
}

// ---------------- GEMM config ------------------------------------------------
#define STG_BYTES 32768
#define SM_BYTES  (2 * STG_BYTES)             // 65536 (projections/head)
#define XG_BYTES  32768
#define SMR_BYTES (2 * STG_BYTES + XG_BYTES)  // 98304 (rec kernel)

#define ACC_DECL                                                                       \
    float acc[4][4][4];                                                                \
    _Pragma("unroll") for (int a_ = 0; a_ < 4; a_++)                                   \
    _Pragma("unroll") for (int b_ = 0; b_ < 4; b_++)                                   \
    _Pragma("unroll") for (int e_ = 0; e_ < 4; e_++) acc[a_][b_][e_] = 0.f;

#define GEMM_COMPUTE_CHUNK(aBase, bBase)                                               \
    _Pragma("unroll")                                                                  \
    for (int k16 = 0; k16 < 4; ++k16) {                                                \
        const int kb8 = k16 * 2 + lk;                                                  \
        u32 bh[4][2];                                                                  \
        _Pragma("unroll")                                                              \
        for (int blk = 0; blk < 2; ++blk) {                                            \
            int row = n_w + blk * 16 + lrow;                                           \
            u32 ad = (bBase) + ((row * 64 + ((kb8 ^ (row & 7)) << 3)) << 1);           \
            u32 r0_, r1_, r2_, r3_;                                                    \
            ldm4(r0_, r1_, r2_, r3_, ad);                                              \
            bh[blk * 2][0] = r0_; bh[blk * 2][1] = r2_;                                \
            bh[blk * 2 + 1][0] = r1_; bh[blk * 2 + 1][1] = r3_;                        \
        }                                                                              \
        _Pragma("unroll")                                                              \
        for (int mt = 0; mt < 4; ++mt) {                                               \
            int row = m_w + mt * 16 + lrow;                                            \
            u32 ad = (aBase) + ((row * 64 + ((kb8 ^ (row & 7)) << 3)) << 1);           \
            u32 af[4];                                                                 \
            ldm4(af[0], af[1], af[2], af[3], ad);                                      \
            _Pragma("unroll")                                                          \
            for (int nt = 0; nt < 4; ++nt) mma16(acc[mt][nt], af, bh[nt]);             \
        }                                                                              \
    }

// ---------------- recurrent GEMM + fused LSTM cell -----------------------------
// gates = h_prev @ W^T + xg_t (addend prefetched to SMEM during mainloop).
__global__ void __launch_bounds__(256, 2)
gemm_rec(const fp16* __restrict__ A, fp16* __restrict__ hout,
         const fp16* __restrict__ W,
         const fp16* __restrict__ xgs, int rowStride,   // xgs = xg slice for step t
         float* __restrict__ c)
{
    extern __shared__ __align__(1024) char sm[];
    const u32 sb = smem_u32(sm);
    const u32 XB = sb + 2 * STG_BYTES;
    char* smx = sm + 2 * STG_BYTES;
    const int tid = threadIdx.x, wid = tid >> 5, lid = tid & 31;
    const int m0 = blockIdx.y * 128;
    const int n0 = blockIdx.x * 128;
    const int tile = n0 >> 8, rowbase = n0 & 255;
    const int m_w = (wid >> 2) * 64, n_w = (wid & 2 ? 64 : 0) + (wid & 1) * 32;
    const int au = tid & 7, ar = tid >> 3;
    const int lrow = lid & 15, lk = lid >> 4;
    const int odd = lid & 1;

    ACC_DECL

    // xg tile prefetch: 128 rows x 128 cols fp16 = 32KB, coalesced 16B chunks.
    {
        int rowL = tid >> 4;
        int coloff = (tid & 15) * 8;
#pragma unroll
        for (int i = 0; i < 8; i++) {
            int row = rowL + i * 16;
            cp16(XB + (u32)((row * 128 + coloff) * 2),
                 xgs + (size_t)(m0 + row) * rowStride + n0 + coloff);
        }
    }

    auto load0 = [&](int stg, int kc) {
        u32 base = sb + stg * STG_BYTES;
#pragma unroll
        for (int i = 0; i < 4; i++) {
            int r = ar + i * 32;
            u32 d = base + ((r * 64 + ((au ^ (r & 7)) << 3)) << 1);
            cp16(d, A + (size_t)(m0 + r) * H_SZ + kc * 64 + au * 8);
        }
        const size_t ib = (size_t)(tile * 4 + kc) * 16384 + (size_t)rowbase * 64;
#pragma unroll
        for (int i = 0; i < 4; i++) {
            int j = tid + i * 256;
            cp16(base + 16384 + j * 16, W + ib + (size_t)j * 8);
        }
        cp_commit();
    };
    load0(0, 0);
#pragma unroll 1
    for (int kc = 0; kc < 4; ++kc) {
        if (kc + 1 < 4) { load0((kc + 1) & 1, kc + 1); cp_wait<1>(); }
        else            { cp_wait<0>(); }
        __syncthreads();
        const u32 aBase = sb + (kc & 1) * STG_BYTES;
        const u32 bBase = aBase + 16384;
        GEMM_COMPUTE_CHUNK(aBase, bBase)
        __syncthreads();
    }

    // fused LSTM cell epilogue (xg from SMEM; ex2-based fast gate math)
#pragma unroll
    for (int mt = 0; mt < 4; ++mt) {
        int r0 = m0 + m_w + mt * 16 + (lid >> 2);
#pragma unroll
        for (int nt = 0; nt < 4; ++nt) {
            float* a4 = acc[mt][nt];
            int p = n0 + n_w + nt * 8 + (lid & 3) * 2;
            int j = p >> 2;
            float s0 = odd ? a4[0] : a4[2];
            float s1 = odd ? a4[1] : a4[3];
            float r0v = __shfl_xor_sync(0xFFFFFFFFu, s0, 1);
            float r1v = __shfl_xor_sync(0xFFFFFFFFu, s1, 1);
            float gi, gf, gg, go;
            int row;
            if (odd) { gi = r0v;  gf = r1v;  gg = a4[2]; go = a4[3]; row = r0 + 8; }
            else     { gi = a4[0]; gf = a4[1]; gg = r0v; go = r1v;  row = r0; }
            int rowL = row - m0;
            int coloff = (p - n0) & ~3;
            const fp16* xs = (const fp16*)(smx + (rowL * 128 + coloff) * 2);
            float2 f01 = __half22float2(*(const __half2*)(xs));
            float2 f23 = __half22float2(*(const __half2*)(xs + 2));
            gi = sig_fast(gi + f01.x);
            gf = sig_fast(gf + f01.y);
            gg = tanh_fast(gg + f23.x);
            go = sig_fast(go + f23.y);
            size_t ci = (size_t)row * H_SZ + j;
            float cn = gf * c[ci] + gi * gg;
            float hn = go * tanh_fast(cn);
            c[ci] = cn;
            hout[ci] = __float2half(hn);
        }
    }
}

// ---------------- generic GEMM (projections fp16-out, head fp32-out) -----------
template <typename OutT>
__global__ void __launch_bounds__(256)
gemm_mma(const fp16* __restrict__ A, int lda,
         const fp16* __restrict__ W, int nkc,
         const float* __restrict__ bias,
         OutT* __restrict__ C, int ldc, int Nvalid)
{
    extern __shared__ __align__(1024) char sm[];
    const u32 sb = smem_u32(sm);
    const int tid = threadIdx.x, wid = tid >> 5, lid = tid & 31;
    const int m0 = blockIdx.y * 128;
    const int n0 = blockIdx.x * 128;
    const int tile = n0 >> 8, rowbase = n0 & 255;
    const int m_w = (wid >> 2) * 64, n_w = (wid & 2 ? 64 : 0) + (wid & 1) * 32;
    const int au = tid & 7, ar = tid >> 3;
    const int lrow = lid & 15, lk = lid >> 4;

    ACC_DECL

    auto load_stage = [&](int s, int kc) {
        u32 base = sb + s * STG_BYTES;
#pragma unroll
        for (int i = 0; i < 4; i++) {
            int r = ar + i * 32;
            u32 d = base + ((r * 64 + ((au ^ (r & 7)) << 3)) << 1);
            cp16(d, A + (size_t)(m0 + r) * lda + (size_t)kc * 64 + au * 8);
        }
        const size_t ib = (size_t)(tile * nkc + kc) * 16384 + (size_t)rowbase * 64;
#pragma unroll
        for (int i = 0; i < 4; i++) {
            int j = tid + i * 256;
            cp16(base + 16384 + j * 16, W + ib + (size_t)j * 8);
        }
        cp_commit();
    };
    load_stage(0, 0);
    for (int kc = 0; kc < nkc; ++kc) {
        if (kc + 1 < nkc) { load_stage((kc + 1) & 1, kc + 1); cp_wait<1>(); }
        else              { cp_wait<0>(); }
        __syncthreads();
        const u32 aBase = sb + (kc & 1) * STG_BYTES;
        const u32 bBase = aBase + 16384;
        GEMM_COMPUTE_CHUNK(aBase, bBase)
        __syncthreads();
    }

#pragma unroll
    for (int mt = 0; mt < 4; ++mt) {
        int r0 = m0 + m_w + mt * 16 + (lid >> 2);
#pragma unroll
        for (int nt = 0; nt < 4; ++nt) {
            int cN = n0 + n_w + nt * 8 + (lid & 3) * 2;
            if (cN < Nvalid) {
                float bx = bias[cN], by = bias[cN + 1];
                float a0 = acc[mt][nt][0] + bx, a1 = acc[mt][nt][1] + by;
                float a2 = acc[mt][nt][2] + bx, a3 = acc[mt][nt][3] + by;
                if constexpr (sizeof(OutT) == 2) {
                    *(__half2*)((fp16*)C + (size_t)r0 * ldc + cN) = __floats2half2_rn(a0, a1);
                    *(__half2*)((fp16*)C + (size_t)(r0 + 8) * ldc + cN) = __floats2half2_rn(a2, a3);
                } else {
                    *(float2*)((float*)C + (size_t)r0 * ldc + cN) = make_float2(a0, a1);
                    *(float2*)((float*)C + (size_t)(r0 + 8) * ldc + cN) = make_float2(a2, a3);
                }
            }
        }
    }
}

// ---------------- t=0 cell (gates = xg_0, c = 0) -------------------------------
__global__ void cell_t0(const fp16* __restrict__ xg, int rowStride,
                        float* __restrict__ c, fp16* __restrict__ hout) {
    int idx = blockIdx.x * blockDim.x + threadIdx.x;
    if (idx >= B_SZ * H_SZ) return;
    int b = idx >> 8, j = idx & 255;
    const fp16* xrow = xg + (size_t)b * rowStride + 4 * j;
    float2 f01 = __half22float2(*(const __half2*)(xrow));
    float2 f23 = __half22float2(*(const __half2*)(xrow + 2));
    float gi = sig_fast(f01.x);
    float gg = tanh_fast(f23.x);
    float go = sig_fast(f23.y);
    float cn = gi * gg;
    float hn = go * tanh_fast(cn);
    c[idx] = cn;
    hout[idx] = __float2half(hn);
}

// ---------------- launch ------------------------------------------------------
extern "C" void kernel_launch(void* const* d_in, const int* in_sizes, int n_in,
                              void* d_out, int out_size)
{
    const int*   car    = (const int*)  d_in[0];
    const int*   reg    = (const int*)  d_in[1];
    const int*   poi    = (const int*)  d_in[2];
    const int*   week   = (const int*)  d_in[3];
    const int*   timei  = (const int*)  d_in[4];
    const float* car_e  = (const float*)d_in[5];
    const float* reg_e  = (const float*)d_in[6];
    const float* poi_e  = (const float*)d_in[7];
    const float* week_e = (const float*)d_in[8];
    const float* time_e = (const float*)d_in[9];
    const float* Wih0   = (const float*)d_in[10];
    const float* Whh0   = (const float*)d_in[11];
    const float* bih0   = (const float*)d_in[12];
    const float* bhh0   = (const float*)d_in[13];
    const float* Wih1   = (const float*)d_in[14];
    const float* Whh1   = (const float*)d_in[15];
    const float* bih1   = (const float*)d_in[16];
    const float* bhh1   = (const float*)d_in[17];
    const float* Wout   = (const float*)d_in[18];
    const float* bout   = (const float*)d_in[19];
    float* out = (float*)d_out;

    fp16 *x, *xg, *h1, *h2a, *h2b, *wih0, *whh0, *wih1, *whh1, *wout;
    float *c0, *c1, *bias0, *bias1;
    cudaGetSymbolAddress((void**)&x,     g_x);
    cudaGetSymbolAddress((void**)&xg,    g_xg);
    cudaGetSymbolAddress((void**)&h1,    g_h1);
    cudaGetSymbolAddress((void**)&h2a,   g_h2a);
    cudaGetSymbolAddress((void**)&h2b,   g_h2b);
    cudaGetSymbolAddress((void**)&c0,    g_c0);
    cudaGetSymbolAddress((void**)&c1,    g_c1);
    cudaGetSymbolAddress((void**)&bias0, g_bias0);
    cudaGetSymbolAddress((void**)&bias1, g_bias1);
    cudaGetSymbolAddress((void**)&wih0,  g_wih0);
    cudaGetSymbolAddress((void**)&whh0,  g_whh0);
    cudaGetSymbolAddress((void**)&wih1,  g_wih1);
    cudaGetSymbolAddress((void**)&whh1,  g_whh1);
    cudaGetSymbolAddress((void**)&wout,  g_wout);

    cudaFuncSetAttribute(gemm_mma<fp16>,  cudaFuncAttributeMaxDynamicSharedMemorySize, SM_BYTES);
    cudaFuncSetAttribute(gemm_mma<float>, cudaFuncAttributeMaxDynamicSharedMemorySize, SM_BYTES);
    cudaFuncSetAttribute(gemm_rec,        cudaFuncAttributeMaxDynamicSharedMemorySize, SMR_BYTES);

    const dim3 recGrid(8, B_SZ / 128);

    // 1: prep + gather
    prep_gather<<<(int)((TOTAL_PG + 255) / 256), 256>>>(
        Wih0, Whh0, Wih1, Whh1, Wout, bih0, bhh0, bih1, bhh1,
        car, reg, poi, week, timei, car_e, reg_e, poi_e, week_e, time_e);
    // 2: layer0 input projection (fp16 out, bias folded; rows b-major)
    gemm_mma<fp16><<<dim3(8, ROWS / 128), 256, SM_BYTES>>>(
        x, XPAD, wih0, 1, bias0, xg, G_SZ, G_SZ);
    // 3: layer0 t=0 cell -> h1[0]
    cell_t0<<<(B_SZ * H_SZ) / 256, 256>>>(xg, XGSTRIDE, c0, h1);
    // 4..12: layer0 t=1..9 (h state lives directly in h1[t])
    for (int t = 1; t < T_SZ; ++t)
        gemm_rec<<<recGrid, 256, SMR_BYTES>>>(
            h1 + (size_t)(t - 1) * B_SZ * H_SZ, h1 + (size_t)t * B_SZ * H_SZ,
            whh0, xg + (size_t)t * G_SZ, XGSTRIDE, c0);
    // 13: layer1 input projection (h1 rows t-major; xg reused, rows t-major)
    gemm_mma<fp16><<<dim3(8, ROWS / 128), 256, SM_BYTES>>>(
        h1, H_SZ, wih1, 4, bias1, xg, G_SZ, G_SZ);
    // 14: layer1 t=0 cell
    cell_t0<<<(B_SZ * H_SZ) / 256, 256>>>(xg, G_SZ, c1, h2a);
    // 15..23: layer1 t=1..9
    {
        fp16* hb[2] = { h2a, h2b };
        for (int t = 1; t < T_SZ; ++t)
            gemm_rec<<<recGrid, 256, SMR_BYTES>>>(
                hb[(t - 1) & 1], hb[t & 1], whh1,
                xg + (size_t)t * B_SZ * G_SZ, G_SZ, c1);
    }
    // 24: output head (h_last = h2b since t=9 is odd)
    gemm_mma<float><<<dim3(4, B_SZ / 128), 256, SM_BYTES>>>(
        h2b, H_SZ, wout, 4, bout, out, N_LABELS, N_LABELS);
}

// round 15
// speedup vs baseline: 2.3523x; 1.7071x over previous
#include <cuda_runtime.h>
#include <cuda_fp16.h>
#include <cstdint>
#include <math.h>

#define B_SZ     16384
#define T_SZ     10
#define H_SZ     256
#define G_SZ     1024
#define N_LABELS 500
#define ROWS     (B_SZ * T_SZ)     // 163840
#define XPAD     64
#define XGSTRIDE 10240             // T_SZ * G_SZ

typedef unsigned long long u64;
typedef unsigned int u32;
typedef __half fp16;

// ---------------- device scratch (no allocations allowed) --------------------
__device__ fp16  g_x   [(size_t)ROWS * XPAD];      // gathered input [b*T+t][64]
__device__ fp16  g_xg  [(size_t)ROWS * G_SZ];      // gate preacts (fp16, permuted, bias folded)
__device__ fp16  g_h1  [(size_t)ROWS * H_SZ];      // layer0 h, [t][b][256] (doubles as L0 state)
__device__ fp16  g_h2a [(size_t)B_SZ * H_SZ];      // layer1 h ping-pong
__device__ fp16  g_h2b [(size_t)B_SZ * H_SZ];
__device__ float g_c0  [(size_t)B_SZ * H_SZ];
__device__ float g_c1  [(size_t)B_SZ * H_SZ];
__device__ float g_bias0[G_SZ];
__device__ float g_bias1[G_SZ];
// weight tile images (fp16, pre-swizzled): [tile*nkc+kc][256 rows][64 cols]
__device__ fp16 g_wih0[4 * 1 * 16384];
__device__ fp16 g_whh0[4 * 4 * 16384];
__device__ fp16 g_wih1[4 * 4 * 16384];
__device__ fp16 g_whh1[4 * 4 * 16384];
__device__ fp16 g_wout[2 * 4 * 16384];

// ---------------- PTX helpers ------------------------------------------------
__device__ __forceinline__ u32 smem_u32(const void* p) {
    u32 a; asm("{ .reg .u64 t; cvta.to.shared.u64 t, %1; cvt.u32.u64 %0, t; }"
               : "=r"(a) : "l"(p));
    return a;
}
__device__ __forceinline__ void cp16(u32 dst, const void* src) {
    asm volatile("cp.async.cg.shared.global [%0], [%1], 16;" :: "r"(dst), "l"(src));
}
__device__ __forceinline__ void cp_commit() { asm volatile("cp.async.commit_group;"); }
template <int N> __device__ __forceinline__ void cp_wait() {
    asm volatile("cp.async.wait_group %0;" :: "n"(N));
}
__device__ __forceinline__ void ldm4(u32& r0, u32& r1, u32& r2, u32& r3, u32 addr) {
    asm volatile("ldmatrix.sync.aligned.m8n8.x4.shared.b16 {%0,%1,%2,%3}, [%4];"
                 : "=r"(r0), "=r"(r1), "=r"(r2), "=r"(r3) : "r"(addr));
}
__device__ __forceinline__ void mma16(float* d, const u32* a, const u32* b) {
    asm volatile("mma.sync.aligned.m16n8k16.row.col.f32.f16.f16.f32 "
                 "{%0,%1,%2,%3}, {%4,%5,%6,%7}, {%8,%9}, {%0,%1,%2,%3};"
                 : "+f"(d[0]), "+f"(d[1]), "+f"(d[2]), "+f"(d[3])
                 : "r"(a[0]), "r"(a[1]), "r"(a[2]), "r"(a[3]), "r"(b[0]), "r"(b[1]));
}
// Gate math: plain libm expf/tanhf ONLY. Both tanh.approx.f32 (R13) and
// __expf/__fdividef (R14) caused 2.3-3.4x kernel slowdowns on this sm_100 part.
__device__ __forceinline__ float sig_g(float x) { return 1.f / (1.f + expf(-x)); }

// ---------------- prep + gather merged (ONE launch) ---------------------------
__device__ __forceinline__ void fill_img(fp16* img, long l, int nkc,
                                         const float* W, int Kw, int Nrows, int perm) {
    int c = (int)(l & 63);
    int r = (int)((l >> 6) & 255);
    long tc = l >> 14;
    int kc = (int)(tc % nkc), nt = (int)(tc / nkc);
    int p = nt * 256 + r;
    int n = perm ? ((p & 3) * 256 + (p >> 2)) : p;
    int k = kc * 64 + c;
    float v = (n < Nrows && k < Kw) ? W[(size_t)n * Kw + k] : 0.f;
    size_t pos = ((size_t)tc * 256 + r) * 64 + (size_t)((((c >> 3) ^ (r & 7)) << 3) | (c & 7));
    img[pos] = __float2half(v);
}

#define SEG0 65536L                  // wih0
#define SEG1 (SEG0 + 262144L)        // whh0
#define SEG2 (SEG1 + 262144L)        // wih1
#define SEG3 (SEG2 + 262144L)        // whh1
#define SEG4 (SEG3 + 131072L)        // wout
#define SEG5 (SEG4 + 1024L)          // biases
#define TOTAL_PG (SEG5 + (long)ROWS * XPAD)

__global__ void prep_gather(const float* __restrict__ Wih0, const float* __restrict__ Whh0,
                            const float* __restrict__ Wih1, const float* __restrict__ Whh1,
                            const float* __restrict__ Wout,
                            const float* __restrict__ bih0, const float* __restrict__ bhh0,
                            const float* __restrict__ bih1, const float* __restrict__ bhh1,
                            const int* __restrict__ car, const int* __restrict__ reg,
                            const int* __restrict__ poi, const int* __restrict__ week,
                            const int* __restrict__ timei,
                            const float* __restrict__ ce, const float* __restrict__ re,
                            const float* __restrict__ pe, const float* __restrict__ we,
                            const float* __restrict__ te) {
    long id = (long)blockIdx.x * blockDim.x + threadIdx.x;
    if (id < SEG0)      fill_img(g_wih0, id,        1, Wih0, 39,  1024, 1);
    else if (id < SEG1) fill_img(g_whh0, id - SEG0, 4, Whh0, 256, 1024, 1);
    else if (id < SEG2) fill_img(g_wih1, id - SEG1, 4, Wih1, 256, 1024, 1);
    else if (id < SEG3) fill_img(g_whh1, id - SEG2, 4, Whh1, 256, 1024, 1);
    else if (id < SEG4) fill_img(g_wout, id - SEG3, 4, Wout, 256, 500,  0);
    else if (id < SEG5) {
        int p = (int)(id - SEG4);
        int j = p >> 2, g = p & 3, n = g * 256 + j;
        g_bias0[p] = bih0[n] + bhh0[n];
        g_bias1[p] = bih1[n] + bhh1[n];
    } else if (id < TOTAL_PG) {
        long i = id - SEG5;
        long r = i / XPAD; int j = (int)(i % XPAD);
        float v = 0.f;
        if      (j < 16) v = ce[(size_t)car  [r] * 16 + j];
        else if (j < 24) v = re[(size_t)reg  [r] * 8  + (j - 16)];
        else if (j < 28) v = pe[(size_t)poi  [r] * 4  + (j - 24)];
        else if (j < 31) v = we[(size_t)week [r] * 3  + (j - 28)];
        else if (j < 39) v = te[(size_t)timei[r] * 8  + (j - 31)];
        g_x[i] = __float2half(v);
    }
}

// ---------------- GEMM config ------------------------------------------------
#define STG_BYTES 32768
#define SM_BYTES  (2 * STG_BYTES)             // 65536 (projections/head, BN=128)
// rec kernel (BN=64): stage = A 16KB + W 8KB = 24KB; x2 stages + xg 16KB = 64KB
#define RSTG_BYTES 24576
#define SMR_BYTES  (2 * RSTG_BYTES + 16384)   // 65536

#define ACC_DECL                                                                       \
    float acc[4][4][4];                                                                \
    _Pragma("unroll") for (int a_ = 0; a_ < 4; a_++)                                   \
    _Pragma("unroll") for (int b_ = 0; b_ < 4; b_++)                                   \
    _Pragma("unroll") for (int e_ = 0; e_ < 4; e_++) acc[a_][b_][e_] = 0.f;

#define GEMM_COMPUTE_CHUNK(aBase, bBase)                                               \
    _Pragma("unroll")                                                                  \
    for (int k16 = 0; k16 < 4; ++k16) {                                                \
        const int kb8 = k16 * 2 + lk;                                                  \
        u32 bh[4][2];                                                                  \
        _Pragma("unroll")                                                              \
        for (int blk = 0; blk < 2; ++blk) {                                            \
            int row = n_w + blk * 16 + lrow;                                           \
            u32 ad = (bBase) + ((row * 64 + ((kb8 ^ (row & 7)) << 3)) << 1);           \
            u32 r0_, r1_, r2_, r3_;                                                    \
            ldm4(r0_, r1_, r2_, r3_, ad);                                              \
            bh[blk * 2][0] = r0_; bh[blk * 2][1] = r2_;                                \
            bh[blk * 2 + 1][0] = r1_; bh[blk * 2 + 1][1] = r3_;                        \
        }                                                                              \
        _Pragma("unroll")                                                              \
        for (int mt = 0; mt < 4; ++mt) {                                               \
            int row = m_w + mt * 16 + lrow;                                            \
            u32 ad = (aBase) + ((row * 64 + ((kb8 ^ (row & 7)) << 3)) << 1);           \
            u32 af[4];                                                                 \
            ldm4(af[0], af[1], af[2], af[3], ad);                                      \
            _Pragma("unroll")                                                          \
            for (int nt = 0; nt < 4; ++nt) mma16(acc[mt][nt], af, bh[nt]);             \
        }                                                                              \
    }

// ---------------- recurrent GEMM + fused LSTM cell (BM=128, BN=64) -------------
// gates = h_prev @ W^T + xg_t; 3 CTAs/SM target for epilogue overlap.
__global__ void __launch_bounds__(256, 3)
gemm_rec(const fp16* __restrict__ A, fp16* __restrict__ hout,
         const fp16* __restrict__ W,
         const fp16* __restrict__ xgs, int rowStride,
         float* __restrict__ c)
{
    extern __shared__ __align__(1024) char sm[];
    const u32 sb = smem_u32(sm);
    const u32 XB = sb + 2 * RSTG_BYTES;
    char* smx = sm + 2 * RSTG_BYTES;
    const int tid = threadIdx.x, wid = tid >> 5, lid = tid & 31;
    const int m0 = blockIdx.y * 128;
    const int n0 = blockIdx.x * 64;
    const int tile = n0 >> 8, rowbase = n0 & 255;
    const int m_w = (wid >> 1) * 32, n_w = (wid & 1) * 32;   // warp tile 32x32
    const int au = tid & 7, ar = tid >> 3;
    const int lrow = lid & 15, lk = lid >> 4;
    const int odd = lid & 1;

    float acc[2][4][4];
#pragma unroll
    for (int a_ = 0; a_ < 2; a_++)
#pragma unroll
        for (int b_ = 0; b_ < 4; b_++)
#pragma unroll
            for (int e_ = 0; e_ < 4; e_++) acc[a_][b_][e_] = 0.f;

    // xg tile prefetch: 128 rows x 64 cols fp16 = 16KB, coalesced 16B chunks.
    {
#pragma unroll
        for (int i = 0; i < 4; i++) {
            int idx = tid + i * 256;            // [0,1024)
            int row = idx >> 3, col8 = (idx & 7) * 8;
            cp16(XB + (u32)((row * 64 + col8) * 2),
                 xgs + (size_t)(m0 + row) * rowStride + n0 + col8);
        }
    }

    auto load0 = [&](int stg, int kc) {
        u32 base = sb + stg * RSTG_BYTES;
        // A: 128 rows x 64 cols (16KB), swizzled
#pragma unroll
        for (int i = 0; i < 4; i++) {
            int r = ar + i * 32;
            u32 d = base + ((r * 64 + ((au ^ (r & 7)) << 3)) << 1);
            cp16(d, A + (size_t)(m0 + r) * H_SZ + kc * 64 + au * 8);
        }
        // W: 64 rows x 64 cols (8KB), pre-swizzled image, linear copy
        const size_t ib = (size_t)(tile * 4 + kc) * 16384 + (size_t)rowbase * 64;
#pragma unroll
        for (int i = 0; i < 2; i++) {
            int j = tid + i * 256;              // [0,512)
            cp16(base + 16384 + j * 16, W + ib + (size_t)j * 8);
        }
        cp_commit();
    };
    load0(0, 0);
#pragma unroll 1
    for (int kc = 0; kc < 4; ++kc) {
        if (kc + 1 < 4) { load0((kc + 1) & 1, kc + 1); cp_wait<1>(); }
        else            { cp_wait<0>(); }
        __syncthreads();
        const u32 aBase = sb + (kc & 1) * RSTG_BYTES;
        const u32 bBase = aBase + 16384;
#pragma unroll
        for (int k16 = 0; k16 < 4; ++k16) {
            const int kb8 = k16 * 2 + lk;
            u32 bh[4][2];
#pragma unroll
            for (int blk = 0; blk < 2; ++blk) {
                int row = n_w + blk * 16 + lrow;
                u32 ad = bBase + ((row * 64 + ((kb8 ^ (row & 7)) << 3)) << 1);
                u32 r0_, r1_, r2_, r3_;
                ldm4(r0_, r1_, r2_, r3_, ad);
                bh[blk * 2][0] = r0_; bh[blk * 2][1] = r2_;
                bh[blk * 2 + 1][0] = r1_; bh[blk * 2 + 1][1] = r3_;
            }
#pragma unroll
            for (int mt = 0; mt < 2; ++mt) {
                int row = m_w + mt * 16 + lrow;
                u32 ad = aBase + ((row * 64 + ((kb8 ^ (row & 7)) << 3)) << 1);
                u32 af[4];
                ldm4(af[0], af[1], af[2], af[3], ad);
#pragma unroll
                for (int nt = 0; nt < 4; ++nt) mma16(acc[mt][nt], af, bh[nt]);
            }
        }
        __syncthreads();
    }

    // fused LSTM cell epilogue (xg from SMEM; libm gate math)
#pragma unroll
    for (int mt = 0; mt < 2; ++mt) {
        int r0 = m0 + m_w + mt * 16 + (lid >> 2);
#pragma unroll
        for (int nt = 0; nt < 4; ++nt) {
            float* a4 = acc[mt][nt];
            int p = n0 + n_w + nt * 8 + (lid & 3) * 2;
            int j = p >> 2;
            float s0 = odd ? a4[0] : a4[2];
            float s1 = odd ? a4[1] : a4[3];
            float r0v = __shfl_xor_sync(0xFFFFFFFFu, s0, 1);
            float r1v = __shfl_xor_sync(0xFFFFFFFFu, s1, 1);
            float gi, gf, gg, go;
            int row;
            if (odd) { gi = r0v;  gf = r1v;  gg = a4[2]; go = a4[3]; row = r0 + 8; }
            else     { gi = a4[0]; gf = a4[1]; gg = r0v; go = r1v;  row = r0; }
            int rowL = row - m0;
            int coloff = (p - n0) & ~3;
            const fp16* xs = (const fp16*)(smx + (rowL * 64 + coloff) * 2);
            float2 f01 = __half22float2(*(const __half2*)(xs));
            float2 f23 = __half22float2(*(const __half2*)(xs + 2));
            gi = sig_g(gi + f01.x);
            gf = sig_g(gf + f01.y);
            gg = tanhf(gg + f23.x);
            go = sig_g(go + f23.y);
            size_t ci = (size_t)row * H_SZ + j;
            float cn = gf * c[ci] + gi * gg;
            float hn = go * tanhf(cn);
            c[ci] = cn;
            hout[ci] = __float2half(hn);
        }
    }
}

// ---------------- generic GEMM (projections fp16-out, head fp32-out) -----------
template <typename OutT>
__global__ void __launch_bounds__(256)
gemm_mma(const fp16* __restrict__ A, int lda,
         const fp16* __restrict__ W, int nkc,
         const float* __restrict__ bias,
         OutT* __restrict__ C, int ldc, int Nvalid)
{
    extern __shared__ __align__(1024) char sm[];
    const u32 sb = smem_u32(sm);
    const int tid = threadIdx.x, wid = tid >> 5, lid = tid & 31;
    const int m0 = blockIdx.y * 128;
    const int n0 = blockIdx.x * 128;
    const int tile = n0 >> 8, rowbase = n0 & 255;
    const int m_w = (wid >> 2) * 64, n_w = (wid & 2 ? 64 : 0) + (wid & 1) * 32;
    const int au = tid & 7, ar = tid >> 3;
    const int lrow = lid & 15, lk = lid >> 4;

    ACC_DECL

    auto load_stage = [&](int s, int kc) {
        u32 base = sb + s * STG_BYTES;
#pragma unroll
        for (int i = 0; i < 4; i++) {
            int r = ar + i * 32;
            u32 d = base + ((r * 64 + ((au ^ (r & 7)) << 3)) << 1);
            cp16(d, A + (size_t)(m0 + r) * lda + (size_t)kc * 64 + au * 8);
        }
        const size_t ib = (size_t)(tile * nkc + kc) * 16384 + (size_t)rowbase * 64;
#pragma unroll
        for (int i = 0; i < 4; i++) {
            int j = tid + i * 256;
            cp16(base + 16384 + j * 16, W + ib + (size_t)j * 8);
        }
        cp_commit();
    };
    load_stage(0, 0);
    for (int kc = 0; kc < nkc; ++kc) {
        if (kc + 1 < nkc) { load_stage((kc + 1) & 1, kc + 1); cp_wait<1>(); }
        else              { cp_wait<0>(); }
        __syncthreads();
        const u32 aBase = sb + (kc & 1) * STG_BYTES;
        const u32 bBase = aBase + 16384;
        GEMM_COMPUTE_CHUNK(aBase, bBase)
        __syncthreads();
    }

#pragma unroll
    for (int mt = 0; mt < 4; ++mt) {
        int r0 = m0 + m_w + mt * 16 + (lid >> 2);
#pragma unroll
        for (int nt = 0; nt < 4; ++nt) {
            int cN = n0 + n_w + nt * 8 + (lid & 3) * 2;
            if (cN < Nvalid) {
                float bx = bias[cN], by = bias[cN + 1];
                float a0 = acc[mt][nt][0] + bx, a1 = acc[mt][nt][1] + by;
                float a2 = acc[mt][nt][2] + bx, a3 = acc[mt][nt][3] + by;
                if constexpr (sizeof(OutT) == 2) {
                    *(__half2*)((fp16*)C + (size_t)r0 * ldc + cN) = __floats2half2_rn(a0, a1);
                    *(__half2*)((fp16*)C + (size_t)(r0 + 8) * ldc + cN) = __floats2half2_rn(a2, a3);
                } else {
                    *(float2*)((float*)C + (size_t)r0 * ldc + cN) = make_float2(a0, a1);
                    *(float2*)((float*)C + (size_t)(r0 + 8) * ldc + cN) = make_float2(a2, a3);
                }
            }
        }
    }
}

// ---------------- t=0 cell (gates = xg_0, c = 0) -------------------------------
__global__ void cell_t0(const fp16* __restrict__ xg, int rowStride,
                        float* __restrict__ c, fp16* __restrict__ hout) {
    int idx = blockIdx.x * blockDim.x + threadIdx.x;
    if (idx >= B_SZ * H_SZ) return;
    int b = idx >> 8, j = idx & 255;
    const fp16* xrow = xg + (size_t)b * rowStride + 4 * j;
    float2 f01 = __half22float2(*(const __half2*)(xrow));
    float2 f23 = __half22float2(*(const __half2*)(xrow + 2));
    float gi = sig_g(f01.x);
    float gg = tanhf(f23.x);
    float go = sig_g(f23.y);
    float cn = gi * gg;
    float hn = go * tanhf(cn);
    c[idx] = cn;
    hout[idx] = __float2half(hn);
}

// ---------------- launch ------------------------------------------------------
extern "C" void kernel_launch(void* const* d_in, const int* in_sizes, int n_in,
                              void* d_out, int out_size)
{
    const int*   car    = (const int*)  d_in[0];
    const int*   reg    = (const int*)  d_in[1];
    const int*   poi    = (const int*)  d_in[2];
    const int*   week   = (const int*)  d_in[3];
    const int*   timei  = (const int*)  d_in[4];
    const float* car_e  = (const float*)d_in[5];
    const float* reg_e  = (const float*)d_in[6];
    const float* poi_e  = (const float*)d_in[7];
    const float* week_e = (const float*)d_in[8];
    const float* time_e = (const float*)d_in[9];
    const float* Wih0   = (const float*)d_in[10];
    const float* Whh0   = (const float*)d_in[11];
    const float* bih0   = (const float*)d_in[12];
    const float* bhh0   = (const float*)d_in[13];
    const float* Wih1   = (const float*)d_in[14];
    const float* Whh1   = (const float*)d_in[15];
    const float* bih1   = (const float*)d_in[16];
    const float* bhh1   = (const float*)d_in[17];
    const float* Wout   = (const float*)d_in[18];
    const float* bout   = (const float*)d_in[19];
    float* out = (float*)d_out;

    fp16 *x, *xg, *h1, *h2a, *h2b, *wih0, *whh0, *wih1, *whh1, *wout;
    float *c0, *c1, *bias0, *bias1;
    cudaGetSymbolAddress((void**)&x,     g_x);
    cudaGetSymbolAddress((void**)&xg,    g_xg);
    cudaGetSymbolAddress((void**)&h1,    g_h1);
    cudaGetSymbolAddress((void**)&h2a,   g_h2a);
    cudaGetSymbolAddress((void**)&h2b,   g_h2b);
    cudaGetSymbolAddress((void**)&c0,    g_c0);
    cudaGetSymbolAddress((void**)&c1,    g_c1);
    cudaGetSymbolAddress((void**)&bias0, g_bias0);
    cudaGetSymbolAddress((void**)&bias1, g_bias1);
    cudaGetSymbolAddress((void**)&wih0,  g_wih0);
    cudaGetSymbolAddress((void**)&whh0,  g_whh0);
    cudaGetSymbolAddress((void**)&wih1,  g_wih1);
    cudaGetSymbolAddress((void**)&whh1,  g_whh1);
    cudaGetSymbolAddress((void**)&wout,  g_wout);

    cudaFuncSetAttribute(gemm_mma<fp16>,  cudaFuncAttributeMaxDynamicSharedMemorySize, SM_BYTES);
    cudaFuncSetAttribute(gemm_mma<float>, cudaFuncAttributeMaxDynamicSharedMemorySize, SM_BYTES);
    cudaFuncSetAttribute(gemm_rec,        cudaFuncAttributeMaxDynamicSharedMemorySize, SMR_BYTES);

    const dim3 recGrid(16, B_SZ / 128);   // BN=64 -> 16 N-tiles

    // 1: prep + gather
    prep_gather<<<(int)((TOTAL_PG + 255) / 256), 256>>>(
        Wih0, Whh0, Wih1, Whh1, Wout, bih0, bhh0, bih1, bhh1,
        car, reg, poi, week, timei, car_e, reg_e, poi_e, week_e, time_e);
    // 2: layer0 input projection (fp16 out, bias folded; rows b-major)
    gemm_mma<fp16><<<dim3(8, ROWS / 128), 256, SM_BYTES>>>(
        x, XPAD, wih0, 1, bias0, xg, G_SZ, G_SZ);
    // 3: layer0 t=0 cell -> h1[0]
    cell_t0<<<(B_SZ * H_SZ) / 256, 256>>>(xg, XGSTRIDE, c0, h1);
    // 4..12: layer0 t=1..9 (h state lives directly in h1[t])
    for (int t = 1; t < T_SZ; ++t)
        gemm_rec<<<recGrid, 256, SMR_BYTES>>>(
            h1 + (size_t)(t - 1) * B_SZ * H_SZ, h1 + (size_t)t * B_SZ * H_SZ,
            whh0, xg + (size_t)t * G_SZ, XGSTRIDE, c0);
    // 13: layer1 input projection (h1 rows t-major; xg reused, rows t-major)
    gemm_mma<fp16><<<dim3(8, ROWS / 128), 256, SM_BYTES>>>(
        h1, H_SZ, wih1, 4, bias1, xg, G_SZ, G_SZ);
    // 14: layer1 t=0 cell
    cell_t0<<<(B_SZ * H_SZ) / 256, 256>>>(xg, G_SZ, c1, h2a);
    // 15..23: layer1 t=1..9
    {
        fp16* hb[2] = { h2a, h2b };
        for (int t = 1; t < T_SZ; ++t)
            gemm_rec<<<recGrid, 256, SMR_BYTES>>>(
                hb[(t - 1) & 1], hb[t & 1], whh1,
                xg + (size_t)t * B_SZ * G_SZ, G_SZ, c1);
    }
    // 24: output head (h_last = h2b since t=9 is odd)
    gemm_mma<float><<<dim3(4, B_SZ / 128), 256, SM_BYTES>>>(
        h2b, H_SZ, wout, 4, bout, out, N_LABELS, N_LABELS);
}

// round 16
// speedup vs baseline: 2.6418x; 1.1231x over previous
#include <cuda_runtime.h>
#include <cuda_fp16.h>
#include <cstdint>
#include <math.h>

#define B_SZ     16384
#define T_SZ     10
#define H_SZ     256
#define G_SZ     1024
#define N_LABELS 500
#define ROWS     (B_SZ * T_SZ)     // 163840
#define XPAD     64
#define XGSTRIDE 10240             // T_SZ * G_SZ
#define BG       ((size_t)B_SZ * G_SZ)

typedef unsigned long long u64;
typedef unsigned int u32;
typedef __half fp16;

// ---------------- device scratch (no allocations allowed) --------------------
__device__ fp16  g_x   [(size_t)ROWS * XPAD];      // gathered input [b*T+t][64]
__device__ fp16  g_xg0 [(size_t)ROWS * G_SZ];      // layer0 preacts, [b][t] (XGSTRIDE)
__device__ fp16  g_xg1 [(size_t)ROWS * G_SZ];      // layer1 preacts, [t][b] (G_SZ)
__device__ fp16  g_h1  [(size_t)ROWS * H_SZ];      // layer0 h, [t][b][256]
__device__ fp16  g_h2a [(size_t)B_SZ * H_SZ];      // layer1 h ping-pong
__device__ fp16  g_h2b [(size_t)B_SZ * H_SZ];
__device__ float g_c0  [(size_t)B_SZ * H_SZ];
__device__ float g_c1  [(size_t)B_SZ * H_SZ];
__device__ float g_bias0[G_SZ];
__device__ float g_bias1[G_SZ];
// weight tile images (fp16, pre-swizzled): [tile*nkc+kc][256 rows][64 cols]
__device__ fp16 g_wih0[4 * 1 * 16384];
__device__ fp16 g_whh0[4 * 4 * 16384];
__device__ fp16 g_wih1[4 * 4 * 16384];
__device__ fp16 g_whh1[4 * 4 * 16384];
__device__ fp16 g_wout[2 * 4 * 16384];

// ---------------- PTX helpers ------------------------------------------------
__device__ __forceinline__ u32 smem_u32(const void* p) {
    u32 a; asm("{ .reg .u64 t; cvta.to.shared.u64 t, %1; cvt.u32.u64 %0, t; }"
               : "=r"(a) : "l"(p));
    return a;
}
__device__ __forceinline__ void cp16(u32 dst, const void* src) {
    asm volatile("cp.async.cg.shared.global [%0], [%1], 16;" :: "r"(dst), "l"(src));
}
__device__ __forceinline__ void cp_commit() { asm volatile("cp.async.commit_group;"); }
template <int N> __device__ __forceinline__ void cp_wait() {
    asm volatile("cp.async.wait_group %0;" :: "n"(N));
}
__device__ __forceinline__ void ldm4(u32& r0, u32& r1, u32& r2, u32& r3, u32 addr) {
    asm volatile("ldmatrix.sync.aligned.m8n8.x4.shared.b16 {%0,%1,%2,%3}, [%4];"
                 : "=r"(r0), "=r"(r1), "=r"(r2), "=r"(r3) : "r"(addr));
}
__device__ __forceinline__ void mma16(float* d, const u32* a, const u32* b) {
    asm volatile("mma.sync.aligned.m16n8k16.row.col.f32.f16.f16.f32 "
                 "{%0,%1,%2,%3}, {%4,%5,%6,%7}, {%8,%9}, {%0,%1,%2,%3};"
                 : "+f"(d[0]), "+f"(d[1]), "+f"(d[2]), "+f"(d[3])
                 : "r"(a[0]), "r"(a[1]), "r"(a[2]), "r"(a[3]), "r"(b[0]), "r"(b[1]));
}
// Gate math: plain libm ONLY (tanh.approx and __expf/__fdividef both measured
// 2.3-3.4x slower on this part — R13/R14).
__device__ __forceinline__ float sig_g(float x) { return 1.f / (1.f + expf(-x)); }

// ---------------- prep + gather merged (ONE launch) ---------------------------
__device__ __forceinline__ void fill_img(fp16* img, long l, int nkc,
                                         const float* W, int Kw, int Nrows, int perm) {
    int c = (int)(l & 63);
    int r = (int)((l >> 6) & 255);
    long tc = l >> 14;
    int kc = (int)(tc % nkc), nt = (int)(tc / nkc);
    int p = nt * 256 + r;
    int n = perm ? ((p & 3) * 256 + (p >> 2)) : p;
    int k = kc * 64 + c;
    float v = (n < Nrows && k < Kw) ? W[(size_t)n * Kw + k] : 0.f;
    size_t pos = ((size_t)tc * 256 + r) * 64 + (size_t)((((c >> 3) ^ (r & 7)) << 3) | (c & 7));
    img[pos] = __float2half(v);
}

#define SEG0 65536L
#define SEG1 (SEG0 + 262144L)
#define SEG2 (SEG1 + 262144L)
#define SEG3 (SEG2 + 262144L)
#define SEG4 (SEG3 + 131072L)
#define SEG5 (SEG4 + 1024L)
#define TOTAL_PG (SEG5 + (long)ROWS * XPAD)

__global__ void prep_gather(const float* __restrict__ Wih0, const float* __restrict__ Whh0,
                            const float* __restrict__ Wih1, const float* __restrict__ Whh1,
                            const float* __restrict__ Wout,
                            const float* __restrict__ bih0, const float* __restrict__ bhh0,
                            const float* __restrict__ bih1, const float* __restrict__ bhh1,
                            const int* __restrict__ car, const int* __restrict__ reg,
                            const int* __restrict__ poi, const int* __restrict__ week,
                            const int* __restrict__ timei,
                            const float* __restrict__ ce, const float* __restrict__ re,
                            const float* __restrict__ pe, const float* __restrict__ we,
                            const float* __restrict__ te) {
    long id = (long)blockIdx.x * blockDim.x + threadIdx.x;
    if (id < SEG0)      fill_img(g_wih0, id,        1, Wih0, 39,  1024, 1);
    else if (id < SEG1) fill_img(g_whh0, id - SEG0, 4, Whh0, 256, 1024, 1);
    else if (id < SEG2) fill_img(g_wih1, id - SEG1, 4, Wih1, 256, 1024, 1);
    else if (id < SEG3) fill_img(g_whh1, id - SEG2, 4, Whh1, 256, 1024, 1);
    else if (id < SEG4) fill_img(g_wout, id - SEG3, 4, Wout, 256, 500,  0);
    else if (id < SEG5) {
        int p = (int)(id - SEG4);
        int j = p >> 2, g = p & 3, n = g * 256 + j;
        g_bias0[p] = bih0[n] + bhh0[n];
        g_bias1[p] = bih1[n] + bhh1[n];
    } else if (id < TOTAL_PG) {
        long i = id - SEG5;
        long r = i / XPAD; int j = (int)(i % XPAD);
        float v = 0.f;
        if      (j < 16) v = ce[(size_t)car  [r] * 16 + j];
        else if (j < 24) v = re[(size_t)reg  [r] * 8  + (j - 16)];
        else if (j < 28) v = pe[(size_t)poi  [r] * 4  + (j - 24)];
        else if (j < 31) v = we[(size_t)week [r] * 3  + (j - 28)];
        else if (j < 39) v = te[(size_t)timei[r] * 8  + (j - 31)];
        g_x[i] = __float2half(v);
    }
}

// ---------------- GEMM config ------------------------------------------------
#define STG_BYTES 32768
#define SM_BYTES  (2 * STG_BYTES)             // 64KB (standalone proj/head)
#define SMR_BYTES (2 * STG_BYTES + 32768)     // 96KB (wf kernel: stages + xg tile)

#define ACC_DECL                                                                       \
    float acc[4][4][4];                                                                \
    _Pragma("unroll") for (int a_ = 0; a_ < 4; a_++)                                   \
    _Pragma("unroll") for (int b_ = 0; b_ < 4; b_++)                                   \
    _Pragma("unroll") for (int e_ = 0; e_ < 4; e_++) acc[a_][b_][e_] = 0.f;

#define GEMM_COMPUTE_CHUNK(aBase, bBase)                                               \
    _Pragma("unroll")                                                                  \
    for (int k16 = 0; k16 < 4; ++k16) {                                                \
        const int kb8 = k16 * 2 + lk;                                                  \
        u32 bh[4][2];                                                                  \
        _Pragma("unroll")                                                              \
        for (int blk = 0; blk < 2; ++blk) {                                            \
            int row = n_w + blk * 16 + lrow;                                           \
            u32 ad = (bBase) + ((row * 64 + ((kb8 ^ (row & 7)) << 3)) << 1);           \
            u32 r0_, r1_, r2_, r3_;                                                    \
            ldm4(r0_, r1_, r2_, r3_, ad);                                              \
            bh[blk * 2][0] = r0_; bh[blk * 2][1] = r2_;                                \
            bh[blk * 2 + 1][0] = r1_; bh[blk * 2 + 1][1] = r3_;                        \
        }                                                                              \
        _Pragma("unroll")                                                              \
        for (int mt = 0; mt < 4; ++mt) {                                               \
            int row = m_w + mt * 16 + lrow;                                            \
            u32 ad = (aBase) + ((row * 64 + ((kb8 ^ (row & 7)) << 3)) << 1);           \
            u32 af[4];                                                                 \
            ldm4(af[0], af[1], af[2], af[3], ad);                                      \
            _Pragma("unroll")                                                          \
            for (int nt = 0; nt < 4; ++nt) mma16(acc[mt][nt], af, bh[nt]);             \
        }                                                                              \
    }

#define LOAD_STAGE(base, A_, W_, kc)                                                   \
    {                                                                                  \
        _Pragma("unroll")                                                              \
        for (int i = 0; i < 4; i++) {                                                  \
            int r = ar + i * 32;                                                       \
            u32 d = (base) + ((r * 64 + ((au ^ (r & 7)) << 3)) << 1);                  \
            cp16(d, A_ + (size_t)(m0 + r) * H_SZ + (kc) * 64 + au * 8);                \
        }                                                                              \
        const size_t ib = (size_t)(tile * 4 + (kc)) * 16384 + (size_t)rowbase * 64;    \
        _Pragma("unroll")                                                              \
        for (int i = 0; i < 4; i++) {                                                  \
            int j = tid + i * 256;                                                     \
            cp16((base) + 16384 + j * 16, W_ + ib + (size_t)j * 8);                    \
        }                                                                              \
        cp_commit();                                                                   \
    }

// ---------------- wavefront kernel: rec + proj + rec jobs in one launch --------
// blockIdx.y < nA          : rec job A  (L0 step; xg b-major, stride strideA)
// nA <= blockIdx.y < nA+nB : proj job   (h1 slice @ Wih1 + bias1 -> xg1 slice)
// else                     : rec job C  (L1 step; xg t-major, stride G_SZ)
__global__ void __launch_bounds__(256, 2)
wf_step(const fp16* __restrict__ Aa, fp16* __restrict__ houta,
        const fp16* __restrict__ Wa, const fp16* __restrict__ xga, int strideA,
        float* __restrict__ ca,
        const fp16* __restrict__ Ab, const fp16* __restrict__ Wb,
        const float* __restrict__ biasb, fp16* __restrict__ Cb,
        const fp16* __restrict__ Ac, fp16* __restrict__ houtc,
        const fp16* __restrict__ Wc, const fp16* __restrict__ xgc,
        float* __restrict__ cc,
        int nA, int nB)
{
    extern __shared__ __align__(1024) char sm[];
    const u32 sb = smem_u32(sm);
    const u32 XB = sb + 2 * STG_BYTES;
    char* smx = sm + 2 * STG_BYTES;
    const int tid = threadIdx.x, wid = tid >> 5, lid = tid & 31;
    const int jy = blockIdx.y;
    const int type = (jy < nA) ? 0 : (jy < nA + nB) ? 1 : 2;
    const int my = jy - ((type == 0) ? 0 : (type == 1) ? nA : (nA + nB));
    const int m0 = my * 128;
    const int n0 = blockIdx.x * 128;
    const int tile = n0 >> 8, rowbase = n0 & 255;
    const int m_w = (wid >> 2) * 64, n_w = (wid & 2 ? 64 : 0) + (wid & 1) * 32;
    const int au = tid & 7, ar = tid >> 3;
    const int lrow = lid & 15, lk = lid >> 4;

    ACC_DECL

    if (type == 1) {
        // ---- proj job: xg1 slice = h1_slice @ Wih1^T + bias1 (fp16 out) ----
        LOAD_STAGE(sb, Ab, Wb, 0)
        for (int kc = 0; kc < 4; ++kc) {
            if (kc + 1 < 4) { LOAD_STAGE(sb + ((kc + 1) & 1) * STG_BYTES, Ab, Wb, kc + 1) cp_wait<1>(); }
            else            { cp_wait<0>(); }
            __syncthreads();
            const u32 aBase = sb + (kc & 1) * STG_BYTES;
            const u32 bBase = aBase + 16384;
            GEMM_COMPUTE_CHUNK(aBase, bBase)
            __syncthreads();
        }
#pragma unroll
        for (int mt = 0; mt < 4; ++mt) {
            int r0 = m0 + m_w + mt * 16 + (lid >> 2);
#pragma unroll
            for (int nt = 0; nt < 4; ++nt) {
                int cN = n0 + n_w + nt * 8 + (lid & 3) * 2;
                float bx = biasb[cN], by = biasb[cN + 1];
                *(__half2*)(Cb + (size_t)r0 * G_SZ + cN) =
                    __floats2half2_rn(acc[mt][nt][0] + bx, acc[mt][nt][1] + by);
                *(__half2*)(Cb + (size_t)(r0 + 8) * G_SZ + cN) =
                    __floats2half2_rn(acc[mt][nt][2] + bx, acc[mt][nt][3] + by);
            }
        }
    } else {
        // ---- rec job: gates = h_prev @ W^T + xg ; fused LSTM cell ----
        const fp16* A    = (type == 0) ? Aa : Ac;
        const fp16* W    = (type == 0) ? Wa : Wc;
        const fp16* xgs  = (type == 0) ? xga : xgc;
        const int rs     = (type == 0) ? strideA : G_SZ;
        float* c         = (type == 0) ? ca : cc;
        fp16* hout       = (type == 0) ? houta : houtc;
        const int odd = lid & 1;

        // xg tile prefetch (32KB, grouped with stage-0 cp.async)
        {
            int rowL = tid >> 4;
            int coloff = (tid & 15) * 8;
#pragma unroll
            for (int i = 0; i < 8; i++) {
                int row = rowL + i * 16;
                cp16(XB + (u32)((row * 128 + coloff) * 2),
                     xgs + (size_t)(m0 + row) * rs + n0 + coloff);
            }
        }
        LOAD_STAGE(sb, A, W, 0)
#pragma unroll 1
        for (int kc = 0; kc < 4; ++kc) {
            if (kc + 1 < 4) { LOAD_STAGE(sb + ((kc + 1) & 1) * STG_BYTES, A, W, kc + 1) cp_wait<1>(); }
            else            { cp_wait<0>(); }
            __syncthreads();
            const u32 aBase = sb + (kc & 1) * STG_BYTES;
            const u32 bBase = aBase + 16384;
            GEMM_COMPUTE_CHUNK(aBase, bBase)
            __syncthreads();
        }
#pragma unroll
        for (int mt = 0; mt < 4; ++mt) {
            int r0 = m0 + m_w + mt * 16 + (lid >> 2);
#pragma unroll
            for (int nt = 0; nt < 4; ++nt) {
                float* a4 = acc[mt][nt];
                int p = n0 + n_w + nt * 8 + (lid & 3) * 2;
                int j = p >> 2;
                float s0 = odd ? a4[0] : a4[2];
                float s1 = odd ? a4[1] : a4[3];
                float r0v = __shfl_xor_sync(0xFFFFFFFFu, s0, 1);
                float r1v = __shfl_xor_sync(0xFFFFFFFFu, s1, 1);
                float gi, gf, gg, go;
                int row;
                if (odd) { gi = r0v;  gf = r1v;  gg = a4[2]; go = a4[3]; row = r0 + 8; }
                else     { gi = a4[0]; gf = a4[1]; gg = r0v; go = r1v;  row = r0; }
                int rowL = row - m0;
                int coloff = (p - n0) & ~3;
                const fp16* xs = (const fp16*)(smx + (rowL * 128 + coloff) * 2);
                float2 f01 = __half22float2(*(const __half2*)(xs));
                float2 f23 = __half22float2(*(const __half2*)(xs + 2));
                gi = sig_g(gi + f01.x);
                gf = sig_g(gf + f01.y);
                gg = tanhf(gg + f23.x);
                go = sig_g(go + f23.y);
                size_t ci = (size_t)row * H_SZ + j;
                float cn = gf * c[ci] + gi * gg;
                float hn = go * tanhf(cn);
                c[ci] = cn;
                hout[ci] = __float2half(hn);
            }
        }
    }
}

// ---------------- standalone GEMM (proj0 fp16-out, head fp32-out) --------------
template <typename OutT>
__global__ void __launch_bounds__(256)
gemm_mma(const fp16* __restrict__ A, int lda,
         const fp16* __restrict__ W, int nkc,
         const float* __restrict__ bias,
         OutT* __restrict__ C, int ldc, int Nvalid)
{
    extern __shared__ __align__(1024) char sm[];
    const u32 sb = smem_u32(sm);
    const int tid = threadIdx.x, wid = tid >> 5, lid = tid & 31;
    const int m0 = blockIdx.y * 128;
    const int n0 = blockIdx.x * 128;
    const int tile = n0 >> 8, rowbase = n0 & 255;
    const int m_w = (wid >> 2) * 64, n_w = (wid & 2 ? 64 : 0) + (wid & 1) * 32;
    const int au = tid & 7, ar = tid >> 3;
    const int lrow = lid & 15, lk = lid >> 4;

    ACC_DECL

    auto load_stage = [&](int s, int kc) {
        u32 base = sb + s * STG_BYTES;
#pragma unroll
        for (int i = 0; i < 4; i++) {
            int r = ar + i * 32;
            u32 d = base + ((r * 64 + ((au ^ (r & 7)) << 3)) << 1);
            cp16(d, A + (size_t)(m0 + r) * lda + (size_t)kc * 64 + au * 8);
        }
        const size_t ib = (size_t)(tile * nkc + kc) * 16384 + (size_t)rowbase * 64;
#pragma unroll
        for (int i = 0; i < 4; i++) {
            int j = tid + i * 256;
            cp16(base + 16384 + j * 16, W + ib + (size_t)j * 8);
        }
        cp_commit();
    };
    load_stage(0, 0);
    for (int kc = 0; kc < nkc; ++kc) {
        if (kc + 1 < nkc) { load_stage((kc + 1) & 1, kc + 1); cp_wait<1>(); }
        else              { cp_wait<0>(); }
        __syncthreads();
        const u32 aBase = sb + (kc & 1) * STG_BYTES;
        const u32 bBase = aBase + 16384;
        GEMM_COMPUTE_CHUNK(aBase, bBase)
        __syncthreads();
    }

#pragma unroll
    for (int mt = 0; mt < 4; ++mt) {
        int r0 = m0 + m_w + mt * 16 + (lid >> 2);
#pragma unroll
        for (int nt = 0; nt < 4; ++nt) {
            int cN = n0 + n_w + nt * 8 + (lid & 3) * 2;
            if (cN < Nvalid) {
                float bx = bias[cN], by = bias[cN + 1];
                float a0 = acc[mt][nt][0] + bx, a1 = acc[mt][nt][1] + by;
                float a2 = acc[mt][nt][2] + bx, a3 = acc[mt][nt][3] + by;
                if constexpr (sizeof(OutT) == 2) {
                    *(__half2*)((fp16*)C + (size_t)r0 * ldc + cN) = __floats2half2_rn(a0, a1);
                    *(__half2*)((fp16*)C + (size_t)(r0 + 8) * ldc + cN) = __floats2half2_rn(a2, a3);
                } else {
                    *(float2*)((float*)C + (size_t)r0 * ldc + cN) = make_float2(a0, a1);
                    *(float2*)((float*)C + (size_t)(r0 + 8) * ldc + cN) = make_float2(a2, a3);
                }
            }
        }
    }
}

// ---------------- t=0 cell (gates = xg_0, c = 0) -------------------------------
__global__ void cell_t0(const fp16* __restrict__ xg, int rowStride,
                        float* __restrict__ c, fp16* __restrict__ hout) {
    int idx = blockIdx.x * blockDim.x + threadIdx.x;
    if (idx >= B_SZ * H_SZ) return;
    int b = idx >> 8, j = idx & 255;
    const fp16* xrow = xg + (size_t)b * rowStride + 4 * j;
    float2 f01 = __half22float2(*(const __half2*)(xrow));
    float2 f23 = __half22float2(*(const __half2*)(xrow + 2));
    float gi = sig_g(f01.x);
    float gg = tanhf(f23.x);
    float go = sig_g(f23.y);
    float cn = gi * gg;
    float hn = go * tanhf(cn);
    c[idx] = cn;
    hout[idx] = __float2half(hn);
}

// ---------------- launch ------------------------------------------------------
extern "C" void kernel_launch(void* const* d_in, const int* in_sizes, int n_in,
                              void* d_out, int out_size)
{
    const int*   car    = (const int*)  d_in[0];
    const int*   reg    = (const int*)  d_in[1];
    const int*   poi    = (const int*)  d_in[2];
    const int*   week   = (const int*)  d_in[3];
    const int*   timei  = (const int*)  d_in[4];
    const float* car_e  = (const float*)d_in[5];
    const float* reg_e  = (const float*)d_in[6];
    const float* poi_e  = (const float*)d_in[7];
    const float* week_e = (const float*)d_in[8];
    const float* time_e = (const float*)d_in[9];
    const float* Wih0   = (const float*)d_in[10];
    const float* Whh0   = (const float*)d_in[11];
    const float* bih0   = (const float*)d_in[12];
    const float* bhh0   = (const float*)d_in[13];
    const float* Wih1   = (const float*)d_in[14];
    const float* Whh1   = (const float*)d_in[15];
    const float* bih1   = (const float*)d_in[16];
    const float* bhh1   = (const float*)d_in[17];
    const float* Wout   = (const float*)d_in[18];
    const float* bout   = (const float*)d_in[19];
    float* out = (float*)d_out;

    fp16 *x, *xg0, *xg1, *h1, *h2a, *h2b, *wih0, *whh0, *wih1, *whh1, *wout;
    float *c0, *c1, *bias0, *bias1;
    cudaGetSymbolAddress((void**)&x,     g_x);
    cudaGetSymbolAddress((void**)&xg0,   g_xg0);
    cudaGetSymbolAddress((void**)&xg1,   g_xg1);
    cudaGetSymbolAddress((void**)&h1,    g_h1);
    cudaGetSymbolAddress((void**)&h2a,   g_h2a);
    cudaGetSymbolAddress((void**)&h2b,   g_h2b);
    cudaGetSymbolAddress((void**)&c0,    g_c0);
    cudaGetSymbolAddress((void**)&c1,    g_c1);
    cudaGetSymbolAddress((void**)&bias0, g_bias0);
    cudaGetSymbolAddress((void**)&bias1, g_bias1);
    cudaGetSymbolAddress((void**)&wih0,  g_wih0);
    cudaGetSymbolAddress((void**)&whh0,  g_whh0);
    cudaGetSymbolAddress((void**)&wih1,  g_wih1);
    cudaGetSymbolAddress((void**)&whh1,  g_whh1);
    cudaGetSymbolAddress((void**)&wout,  g_wout);

    cudaFuncSetAttribute(gemm_mma<fp16>,  cudaFuncAttributeMaxDynamicSharedMemorySize, SM_BYTES);
    cudaFuncSetAttribute(gemm_mma<float>, cudaFuncAttributeMaxDynamicSharedMemorySize, SM_BYTES);
    cudaFuncSetAttribute(wf_step,         cudaFuncAttributeMaxDynamicSharedMemorySize, SMR_BYTES);

    fp16* hb[2] = { h2a, h2b };
    auto h1s = [&](int t) { return h1 + (size_t)t * B_SZ * H_SZ; };
    auto x1s = [&](int t) { return xg1 + (size_t)t * BG; };

    // 1: prep + gather
    prep_gather<<<(int)((TOTAL_PG + 255) / 256), 256>>>(
        Wih0, Whh0, Wih1, Whh1, Wout, bih0, bhh0, bih1, bhh1,
        car, reg, poi, week, timei, car_e, reg_e, poi_e, week_e, time_e);
    // 2: layer0 input projection (batched, fp16 out; xg0 b-major)
    gemm_mma<fp16><<<dim3(8, ROWS / 128), 256, SM_BYTES>>>(
        x, XPAD, wih0, 1, bias0, xg0, G_SZ, G_SZ);
    // 3: layer0 t=0 cell -> h1[0]
    cell_t0<<<(B_SZ * H_SZ) / 256, 256>>>(xg0, XGSTRIDE, c0, h1s(0));

    // 4: t=1 — L0rec(1) + proj1(0)
    wf_step<<<dim3(8, 256), 256, SMR_BYTES>>>(
        h1s(0), h1s(1), whh0, xg0 + 1 * G_SZ, XGSTRIDE, c0,
        h1s(0), wih1, bias1, x1s(0),
        h1s(0), h1s(1), whh0, xg0, c0,        // unused job-C slots (valid ptrs)
        128, 128);
    // 5: layer1 t=0 cell (needs xg1[0])
    cell_t0<<<(B_SZ * H_SZ) / 256, 256>>>(x1s(0), G_SZ, c1, hb[0]);

    // 6..13: t=2..9 — L0rec(t) + proj1(t-1) + L1rec(t-2) [from t=3]
    for (int t = 2; t <= 9; ++t) {
        int s = t - 2;
        int nC = (s >= 1) ? 128 : 0;
        wf_step<<<dim3(8, 256 + nC), 256, SMR_BYTES>>>(
            h1s(t - 1), h1s(t), whh0, xg0 + (size_t)t * G_SZ, XGSTRIDE, c0,
            h1s(t - 1), wih1, bias1, x1s(t - 1),
            (s >= 1) ? hb[(s - 1) & 1] : h1s(0), hb[s & 1], whh1, x1s(s), c1,
            128, 128);
    }
    // 14: proj1(9) + L1rec(8)
    wf_step<<<dim3(8, 256), 256, SMR_BYTES>>>(
        h1s(9), h1s(9), whh0, xg0, XGSTRIDE, c0,   // unused job-A slots
        h1s(9), wih1, bias1, x1s(9),
        hb[1], hb[0], whh1, x1s(8), c1,
        0, 128);
    // 15: L1rec(9)
    wf_step<<<dim3(8, 128), 256, SMR_BYTES>>>(
        h1s(9), h1s(9), whh0, xg0, XGSTRIDE, c0,
        h1s(9), wih1, bias1, x1s(9),
        hb[0], hb[1], whh1, x1s(9), c1,
        0, 0);
    // 16: output head (h_last = hb[1])
    gemm_mma<float><<<dim3(4, B_SZ / 128), 256, SM_BYTES>>>(
        hb[1], H_SZ, wout, 4, bout, out, N_LABELS, N_LABELS);
}